// round 6
// baseline (speedup 1.0000x reference)
#include <cuda_runtime.h>
#include <math.h>

#define N_USERS 100000
#define N_ITEMS 50000
#define N_NODES 150000
#define EMB 64
#define NINT 128
#define MAX_EDGES 4000000

#define N4 ((N_NODES + 3) / 4)
#define NBLK ((N4 + 1023) / 1024)

// ---------------- static device scratch ----------------
__device__ int    g_deg[N_NODES];
__device__ float  g_dis[N_NODES];
__device__ int    g_rowptr[N_NODES + 1];
__device__ int    g_cursor[N_NODES];
__device__ int    g_ecol[MAX_EDGES];
__device__ volatile unsigned long long g_state[NBLK];
__device__ float  g_embA[(size_t)N_NODES * EMB];
__device__ float  g_embB[(size_t)N_NODES * EMB];
__device__ float  g_embS[(size_t)N_NODES * EMB];   // dis-scaled spmm input (fp32)

// ---------------- packed fp32x2 helpers ----------------
__device__ __forceinline__ unsigned long long fma2(unsigned long long a,
                                                   unsigned long long b,
                                                   unsigned long long c) {
    unsigned long long d;
    asm("fma.rn.f32x2 %0, %1, %2, %3;" : "=l"(d) : "l"(a), "l"(b), "l"(c));
    return d;
}
__device__ __forceinline__ unsigned long long pk2(float x, float y) {
    unsigned long long r;
    asm("mov.b64 %0, {%1, %2};" : "=l"(r) : "f"(x), "f"(y));
    return r;
}
__device__ __forceinline__ float2 upk(unsigned long long v) {
    float2 f;
    asm("mov.b64 {%0, %1}, %2;" : "=f"(f.x), "=f"(f.y) : "l"(v));
    return f;
}

// ---------------- precompute ----------------
__global__ void hist_kernel(const int* __restrict__ h, int n) {
    int stride = gridDim.x * blockDim.x;
    for (int i = blockIdx.x * blockDim.x + threadIdx.x; i < n; i += stride)
        atomicAdd(&g_deg[h[i]], 1);
}

// single-pass decoupled-lookback scan: deg -> rowptr/cursor (exclusive), dis
__global__ __launch_bounds__(1024) void scan_kernel(int n_edges) {
    __shared__ int ws[32];
    __shared__ int s_excl;
    const int t = threadIdx.x, b = blockIdx.x;
    const int lane = t & 31, wid = t >> 5;
    const int idx = b * 1024 + t;
    int4 v = (idx < N4) ? ((const int4*)g_deg)[idx] : make_int4(0, 0, 0, 0);
    int s = v.x + v.y + v.z + v.w;
    int x = s;
    #pragma unroll
    for (int o = 1; o < 32; o <<= 1) {
        int y = __shfl_up_sync(0xffffffffu, x, o);
        if (lane >= o) x += y;
    }
    if (lane == 31) ws[wid] = x;
    __syncthreads();
    if (wid == 0) {
        int z = ws[lane];
        #pragma unroll
        for (int o = 1; o < 32; o <<= 1) {
            int y = __shfl_up_sync(0xffffffffu, z, o);
            if (lane >= o) z += y;
        }
        ws[lane] = z;
    }
    __syncthreads();
    const int total = ws[31];

    if (t == 0) {
        if (b == 0) {
            g_state[0] = (2ull << 32) | (unsigned)total;
            s_excl = 0;
        } else {
            g_state[b] = (1ull << 32) | (unsigned)total;
            int excl = 0;
            int p = b - 1;
            while (true) {
                unsigned long long st;
                do { st = g_state[p]; } while ((st >> 32) == 0ull);
                excl += (int)(unsigned)st;
                if ((st >> 32) == 2ull) break;
                p--;
            }
            g_state[b] = (2ull << 32) | (unsigned)(excl + total);
            s_excl = excl;
        }
    }
    __syncthreads();

    int base = s_excl + ((wid > 0) ? ws[wid - 1] : 0) + (x - s);
    if (idx < N4) {
        int i = idx * 4;
        int e0 = base, e1 = e0 + v.x, e2 = e1 + v.y, e3 = e2 + v.z;
        g_rowptr[i + 0] = e0; g_cursor[i + 0] = e0;
        g_rowptr[i + 1] = e1; g_cursor[i + 1] = e1;
        g_rowptr[i + 2] = e2; g_cursor[i + 2] = e2;
        g_rowptr[i + 3] = e3; g_cursor[i + 3] = e3;
        g_dis[i + 0] = (v.x > 0) ? rsqrtf((float)v.x) : 0.0f;
        g_dis[i + 1] = (v.y > 0) ? rsqrtf((float)v.y) : 0.0f;
        g_dis[i + 2] = (v.z > 0) ? rsqrtf((float)v.z) : 0.0f;
        g_dis[i + 3] = (v.w > 0) ? rsqrtf((float)v.w) : 0.0f;
    }
    if (b == 0 && t == 0) g_rowptr[N_NODES] = n_edges;
}

// fused: CSR column scatter + embA/out/S initialization
__global__ void scatter_init_kernel(const int* __restrict__ h, const int* __restrict__ t,
                                    int n,
                                    const float* __restrict__ u, const float* __restrict__ it,
                                    float* __restrict__ embA, float* __restrict__ out,
                                    float* __restrict__ S) {
    const int stride = gridDim.x * blockDim.x;
    const int tid0 = blockIdx.x * blockDim.x + threadIdx.x;
    const int total4 = N_NODES * EMB / 4;
    const int ub4 = N_USERS * EMB / 4;
    const float third = 1.0f / 3.0f;
    for (int i = tid0; i < total4; i += stride) {
        float4 v = (i < ub4) ? ((const float4*)u)[i] : ((const float4*)it)[i - ub4];
        ((float4*)embA)[i] = v;
        ((float4*)out)[i] = make_float4(v.x * third, v.y * third, v.z * third, v.w * third);
        float d = g_dis[i >> 4];
        ((float4*)S)[i] = make_float4(v.x * d, v.y * d, v.z * d, v.w * d);
    }
    for (int i = tid0; i < n; i += stride) {
        int hh = h[i];
        int pos = atomicAdd(&g_cursor[hh], 1);
        g_ecol[pos] = t[i];
    }
}

// ---------------- SPMM: warp per node, 16 lanes per row, 2 edges/step ----------------
__global__ __launch_bounds__(256) void spmm_kernel(const float* __restrict__ S,
                                                   float* __restrict__ xout) {
    const int lane = threadIdx.x & 31;
    const int grp = lane >> 4;          // 0: even edge of pair, 1: odd edge
    const int q = lane & 15;            // float4 slot within the 64-float row
    const int n = (blockIdx.x << 3) + (threadIdx.x >> 5);
    if (n >= N_NODES) return;
    const int beg = g_rowptr[n], end = g_rowptr[n + 1];

    unsigned long long a0 = 0ull, a1 = 0ull;   // packed float4 accumulator
    const unsigned long long one2 = 0x3f8000003f800000ull;
    int j = beg;

    // 4 pairs (8 edges) per iteration
    for (; j + 8 <= end; j += 8) {
        int c0 = g_ecol[j + 0 + grp];
        int c1 = g_ecol[j + 2 + grp];
        int c2 = g_ecol[j + 4 + grp];
        int c3 = g_ecol[j + 6 + grp];
        float4 v0 = *(const float4*)(S + (size_t)c0 * EMB + q * 4);
        float4 v1 = *(const float4*)(S + (size_t)c1 * EMB + q * 4);
        float4 v2 = *(const float4*)(S + (size_t)c2 * EMB + q * 4);
        float4 v3 = *(const float4*)(S + (size_t)c3 * EMB + q * 4);
        a0 = fma2(pk2(v0.x, v0.y), one2, a0);
        a1 = fma2(pk2(v0.z, v0.w), one2, a1);
        a0 = fma2(pk2(v1.x, v1.y), one2, a0);
        a1 = fma2(pk2(v1.z, v1.w), one2, a1);
        a0 = fma2(pk2(v2.x, v2.y), one2, a0);
        a1 = fma2(pk2(v2.z, v2.w), one2, a1);
        a0 = fma2(pk2(v3.x, v3.y), one2, a0);
        a1 = fma2(pk2(v3.z, v3.w), one2, a1);
    }
    // remaining pairs
    for (; j + 2 <= end; j += 2) {
        int c = g_ecol[j + grp];
        float4 v = *(const float4*)(S + (size_t)c * EMB + q * 4);
        a0 = fma2(pk2(v.x, v.y), one2, a0);
        a1 = fma2(pk2(v.z, v.w), one2, a1);
    }
    // odd tail edge: group 0 only
    if (j < end && grp == 0) {
        int c = g_ecol[j];
        float4 v = *(const float4*)(S + (size_t)c * EMB + q * 4);
        a0 = fma2(pk2(v.x, v.y), one2, a0);
        a1 = fma2(pk2(v.z, v.w), one2, a1);
    }

    // merge the two half-warp accumulators (lane i <-> lane i+16 hold same columns)
    float2 f0 = upk(a0), f1 = upk(a1);
    f0.x += __shfl_xor_sync(0xffffffffu, f0.x, 16);
    f0.y += __shfl_xor_sync(0xffffffffu, f0.y, 16);
    f1.x += __shfl_xor_sync(0xffffffffu, f1.x, 16);
    f1.y += __shfl_xor_sync(0xffffffffu, f1.y, 16);

    if (grp == 0) {
        float dn = g_dis[n];
        *(float4*)(xout + (size_t)n * EMB + q * 4) =
            make_float4(f0.x * dn, f0.y * dn, f1.x * dn, f1.y * dn);
    }
}

// ---------------- fused intent: y = softmax(X@W)@W^T; xio += y; out += xio/3 ----------------
#define LD1 130
#define LDP 130
#define LDW2 68
#define R1_FLOATS 16640
#define SMEMF_BYTES ((R1_FLOATS + 128 * LDW2) * 4)   // 101376 B

__global__ __launch_bounds__(256, 2) void fused_intent_kernel(
    const float* __restrict__ xin, const float* __restrict__ W,
    float* __restrict__ xio, float* __restrict__ out,
    float* __restrict__ Sout) {
    extern __shared__ float smem[];
    float* sXT = smem;                    // [64][LD1]
    float* sW  = smem + 64 * LD1;         // [64][128]
    float* sPT = smem;                    // [128][LDP]  (aliases after sync)
    float* sWT = smem + R1_FLOATS;        // [128][LDW2]

    const int tid = threadIdx.x;
    const int node0 = blockIdx.x * 128;

    for (int i = tid; i < 64 * 128 / 4; i += 256)
        *(float4*)(sW + i * 4) = *(const float4*)(W + i * 4);
    for (int i = tid; i < 64 * 128; i += 256) {
        int k = i >> 7, j = i & 127;
        sWT[j * LDW2 + k] = W[i];
    }
    for (int i = tid; i < 128 * 16; i += 256) {
        int m = i >> 4;
        int k4 = (i & 15) << 2;
        int nd = node0 + m;
        float4 v = (nd < N_NODES) ? *(const float4*)(xin + (size_t)nd * EMB + k4)
                                  : make_float4(0.f, 0.f, 0.f, 0.f);
        sXT[(k4 + 0) * LD1 + m] = v.x;
        sXT[(k4 + 1) * LD1 + m] = v.y;
        sXT[(k4 + 2) * LD1 + m] = v.z;
        sXT[(k4 + 3) * LD1 + m] = v.w;
    }
    __syncthreads();

    const int tj = tid & 15, tm = tid >> 4;
    const int m0 = tm * 8, j0 = tj * 8;
    unsigned long long acc[4][8];
    #pragma unroll
    for (int p = 0; p < 4; p++)
        #pragma unroll
        for (int c = 0; c < 8; c++) acc[p][c] = 0ull;

    #pragma unroll 8
    for (int k = 0; k < 64; k++) {
        unsigned long long a2[4];
        #pragma unroll
        for (int p = 0; p < 4; p++)
            a2[p] = *(const unsigned long long*)(sXT + k * LD1 + m0 + 2 * p);
        float4 b0 = *(const float4*)(sW + k * 128 + j0);
        float4 b1 = *(const float4*)(sW + k * 128 + j0 + 4);
        unsigned long long b2[8];
        b2[0] = pk2(b0.x, b0.x); b2[1] = pk2(b0.y, b0.y);
        b2[2] = pk2(b0.z, b0.z); b2[3] = pk2(b0.w, b0.w);
        b2[4] = pk2(b1.x, b1.x); b2[5] = pk2(b1.y, b1.y);
        b2[6] = pk2(b1.z, b1.z); b2[7] = pk2(b1.w, b1.w);
        #pragma unroll
        for (int p = 0; p < 4; p++)
            #pragma unroll
            for (int c = 0; c < 8; c++)
                acc[p][c] = fma2(a2[p], b2[c], acc[p][c]);
    }
    __syncthreads();

    #pragma unroll
    for (int p = 0; p < 4; p++) {
        float lo[8], hi[8];
        #pragma unroll
        for (int c = 0; c < 8; c++) {
            float2 t = upk(acc[p][c]);
            lo[c] = t.x; hi[c] = t.y;
        }
        float mx0 = lo[0], mx1 = hi[0];
        #pragma unroll
        for (int c = 1; c < 8; c++) { mx0 = fmaxf(mx0, lo[c]); mx1 = fmaxf(mx1, hi[c]); }
        #pragma unroll
        for (int o = 8; o > 0; o >>= 1) {
            mx0 = fmaxf(mx0, __shfl_xor_sync(0xffffffffu, mx0, o));
            mx1 = fmaxf(mx1, __shfl_xor_sync(0xffffffffu, mx1, o));
        }
        float s0 = 0.f, s1 = 0.f;
        #pragma unroll
        for (int c = 0; c < 8; c++) {
            lo[c] = __expf(lo[c] - mx0); s0 += lo[c];
            hi[c] = __expf(hi[c] - mx1); s1 += hi[c];
        }
        #pragma unroll
        for (int o = 8; o > 0; o >>= 1) {
            s0 += __shfl_xor_sync(0xffffffffu, s0, o);
            s1 += __shfl_xor_sync(0xffffffffu, s1, o);
        }
        float i0 = 1.0f / s0, i1 = 1.0f / s1;
        #pragma unroll
        for (int c = 0; c < 8; c++)
            *(unsigned long long*)(sPT + (size_t)(j0 + c) * LDP + m0 + 2 * p) =
                pk2(lo[c] * i0, hi[c] * i1);
    }
    __syncthreads();

    const int tn = tid & 15, tm2 = tid >> 4;
    const int mm0 = tm2 * 8, n0 = tn * 4;
    unsigned long long acc2[4][4];
    #pragma unroll
    for (int p = 0; p < 4; p++)
        #pragma unroll
        for (int c = 0; c < 4; c++) acc2[p][c] = 0ull;

    #pragma unroll 8
    for (int j = 0; j < 128; j++) {
        unsigned long long a2[4];
        #pragma unroll
        for (int p = 0; p < 4; p++)
            a2[p] = *(const unsigned long long*)(sPT + (size_t)j * LDP + mm0 + 2 * p);
        float4 b = *(const float4*)(sWT + j * LDW2 + n0);
        unsigned long long b2[4];
        b2[0] = pk2(b.x, b.x); b2[1] = pk2(b.y, b.y);
        b2[2] = pk2(b.z, b.z); b2[3] = pk2(b.w, b.w);
        #pragma unroll
        for (int p = 0; p < 4; p++)
            #pragma unroll
            for (int c = 0; c < 4; c++)
                acc2[p][c] = fma2(a2[p], b2[c], acc2[p][c]);
    }

    const float third = 1.0f / 3.0f;
    #pragma unroll
    for (int p = 0; p < 4; p++) {
        float2 t0 = upk(acc2[p][0]);
        float2 t1 = upk(acc2[p][1]);
        float2 t2 = upk(acc2[p][2]);
        float2 t3 = upk(acc2[p][3]);
        #pragma unroll
        for (int h = 0; h < 2; h++) {
            int nd = node0 + mm0 + 2 * p + h;
            if (nd < N_NODES) {
                size_t idx = (size_t)nd * EMB + n0;
                float y0 = h ? t0.y : t0.x, y1 = h ? t1.y : t1.x;
                float y2 = h ? t2.y : t2.x, y3 = h ? t3.y : t3.x;
                float4 g = *(const float4*)(xio + idx);
                float4 y = make_float4(y0 + g.x, y1 + g.y, y2 + g.z, y3 + g.w);
                *(float4*)(xio + idx) = y;
                float4 o = *(const float4*)(out + idx);
                o.x += y.x * third; o.y += y.y * third;
                o.z += y.z * third; o.w += y.w * third;
                *(float4*)(out + idx) = o;
                if (Sout) {
                    float d = g_dis[nd];
                    *(float4*)(Sout + idx) =
                        make_float4(y.x * d, y.y * d, y.z * d, y.w * d);
                }
            }
        }
    }
}

// ---------------- launch ----------------
extern "C" void kernel_launch(void* const* d_in, const int* in_sizes, int n_in,
                              void* d_out, int out_size) {
    const float* user = (const float*)d_in[0];
    const float* item = (const float*)d_in[1];
    const float* W    = (const float*)d_in[2];
    const int*   hix  = (const int*)d_in[3];
    const int*   tix  = (const int*)d_in[4];
    const int n_edges = in_sizes[3];
    float* out = (float*)d_out;

    cudaFuncSetAttribute(fused_intent_kernel,
                         cudaFuncAttributeMaxDynamicSharedMemorySize, SMEMF_BYTES);

    float *A, *B, *S;
    void *degp, *statep;
    cudaGetSymbolAddress((void**)&A, g_embA);
    cudaGetSymbolAddress((void**)&B, g_embB);
    cudaGetSymbolAddress((void**)&S, g_embS);
    cudaGetSymbolAddress(&degp, g_deg);
    cudaGetSymbolAddress(&statep, g_state);

    const int TB = 256;
    cudaMemsetAsync(degp, 0, N_NODES * sizeof(int));
    cudaMemsetAsync(statep, 0, NBLK * sizeof(unsigned long long));

    hist_kernel<<<4096, TB>>>(hix, n_edges);                               // launch 1
    scan_kernel<<<NBLK, 1024>>>(n_edges);                                  // launch 2
    scatter_init_kernel<<<4096, TB>>>(hix, tix, n_edges, user, item, A, out, S); // launch 3

    const int spmm_blocks = (N_NODES + 7) / 8;
    const int tile_blocks = (N_NODES + 127) / 128;

    // layer 0
    spmm_kernel<<<spmm_blocks, TB>>>(S, B);                                // launch 4 (profiled)
    fused_intent_kernel<<<tile_blocks, TB, SMEMF_BYTES>>>(A, W, B, out, S);
    // layer 1
    spmm_kernel<<<spmm_blocks, TB>>>(S, A);
    fused_intent_kernel<<<tile_blocks, TB, SMEMF_BYTES>>>(B, W, A, out, nullptr);
}

// round 8
// speedup vs baseline: 1.0037x; 1.0037x over previous
#include <cuda_runtime.h>
#include <math.h>

#define N_USERS 100000
#define N_ITEMS 50000
#define N_NODES 150000
#define EMB 64
#define NINT 128
#define MAX_EDGES 4000000

#define N4 ((N_NODES + 3) / 4)
#define NBLK ((N4 + 1023) / 1024)

// ---------------- static device scratch ----------------
__device__ int    g_deg[N_NODES];
__device__ float  g_dis[N_NODES];
__device__ int    g_rowptr[N_NODES + 1];
__device__ int    g_cursor[N_NODES];
__device__ int    g_ecol[MAX_EDGES];
__device__ volatile unsigned long long g_state[NBLK];
__device__ float  g_embA[(size_t)N_NODES * EMB];
__device__ float  g_embB[(size_t)N_NODES * EMB];
__device__ float  g_embS[(size_t)N_NODES * EMB];   // dis-scaled spmm input (fp32)

// ---------------- packed fp32x2 helpers ----------------
__device__ __forceinline__ unsigned long long fma2(unsigned long long a,
                                                   unsigned long long b,
                                                   unsigned long long c) {
    unsigned long long d;
    asm("fma.rn.f32x2 %0, %1, %2, %3;" : "=l"(d) : "l"(a), "l"(b), "l"(c));
    return d;
}
__device__ __forceinline__ unsigned long long pk2(float x, float y) {
    unsigned long long r;
    asm("mov.b64 %0, {%1, %2};" : "=l"(r) : "f"(x), "f"(y));
    return r;
}
__device__ __forceinline__ float2 upk(unsigned long long v) {
    float2 f;
    asm("mov.b64 {%0, %1}, %2;" : "=f"(f.x), "=f"(f.y) : "l"(v));
    return f;
}

// ---------------- precompute ----------------
__global__ void hist_kernel(const int* __restrict__ h, int n) {
    int stride = gridDim.x * blockDim.x;
    for (int i = blockIdx.x * blockDim.x + threadIdx.x; i < n; i += stride)
        atomicAdd(&g_deg[h[i]], 1);
}

// single-pass decoupled-lookback scan: deg -> rowptr/cursor (exclusive), dis
__global__ __launch_bounds__(1024) void scan_kernel(int n_edges) {
    __shared__ int ws[32];
    __shared__ int s_excl;
    const int t = threadIdx.x, b = blockIdx.x;
    const int lane = t & 31, wid = t >> 5;
    const int idx = b * 1024 + t;
    int4 v = (idx < N4) ? ((const int4*)g_deg)[idx] : make_int4(0, 0, 0, 0);
    int s = v.x + v.y + v.z + v.w;
    int x = s;
    #pragma unroll
    for (int o = 1; o < 32; o <<= 1) {
        int y = __shfl_up_sync(0xffffffffu, x, o);
        if (lane >= o) x += y;
    }
    if (lane == 31) ws[wid] = x;
    __syncthreads();
    if (wid == 0) {
        int z = ws[lane];
        #pragma unroll
        for (int o = 1; o < 32; o <<= 1) {
            int y = __shfl_up_sync(0xffffffffu, z, o);
            if (lane >= o) z += y;
        }
        ws[lane] = z;
    }
    __syncthreads();
    const int total = ws[31];

    if (t == 0) {
        if (b == 0) {
            g_state[0] = (2ull << 32) | (unsigned)total;
            s_excl = 0;
        } else {
            g_state[b] = (1ull << 32) | (unsigned)total;
            int excl = 0;
            int p = b - 1;
            while (true) {
                unsigned long long st;
                do { st = g_state[p]; } while ((st >> 32) == 0ull);
                excl += (int)(unsigned)st;
                if ((st >> 32) == 2ull) break;
                p--;
            }
            g_state[b] = (2ull << 32) | (unsigned)(excl + total);
            s_excl = excl;
        }
    }
    __syncthreads();

    int base = s_excl + ((wid > 0) ? ws[wid - 1] : 0) + (x - s);
    if (idx < N4) {
        int i = idx * 4;
        int e0 = base, e1 = e0 + v.x, e2 = e1 + v.y, e3 = e2 + v.z;
        g_rowptr[i + 0] = e0; g_cursor[i + 0] = e0;
        g_rowptr[i + 1] = e1; g_cursor[i + 1] = e1;
        g_rowptr[i + 2] = e2; g_cursor[i + 2] = e2;
        g_rowptr[i + 3] = e3; g_cursor[i + 3] = e3;
        g_dis[i + 0] = (v.x > 0) ? rsqrtf((float)v.x) : 0.0f;
        g_dis[i + 1] = (v.y > 0) ? rsqrtf((float)v.y) : 0.0f;
        g_dis[i + 2] = (v.z > 0) ? rsqrtf((float)v.z) : 0.0f;
        g_dis[i + 3] = (v.w > 0) ? rsqrtf((float)v.w) : 0.0f;
    }
    if (b == 0 && t == 0) g_rowptr[N_NODES] = n_edges;
}

// fused: CSR column scatter + embA/out/S initialization
__global__ void scatter_init_kernel(const int* __restrict__ h, const int* __restrict__ t,
                                    int n,
                                    const float* __restrict__ u, const float* __restrict__ it,
                                    float* __restrict__ embA, float* __restrict__ out,
                                    float* __restrict__ S) {
    const int stride = gridDim.x * blockDim.x;
    const int tid0 = blockIdx.x * blockDim.x + threadIdx.x;
    const int total4 = N_NODES * EMB / 4;
    const int ub4 = N_USERS * EMB / 4;
    const float third = 1.0f / 3.0f;
    for (int i = tid0; i < total4; i += stride) {
        float4 v = (i < ub4) ? ((const float4*)u)[i] : ((const float4*)it)[i - ub4];
        ((float4*)embA)[i] = v;
        ((float4*)out)[i] = make_float4(v.x * third, v.y * third, v.z * third, v.w * third);
        float d = g_dis[i >> 4];
        ((float4*)S)[i] = make_float4(v.x * d, v.y * d, v.z * d, v.w * d);
    }
    for (int i = tid0; i < n; i += stride) {
        int hh = h[i];
        int pos = atomicAdd(&g_cursor[hh], 1);
        g_ecol[pos] = t[i];
    }
}

// ---------------- SPMM: warp/node, 16 lanes/row, software-pipelined (scalar idx) ----------------
__global__ __launch_bounds__(256) void spmm_kernel(const float* __restrict__ S,
                                                   float* __restrict__ xout) {
    const int lane = threadIdx.x & 31;
    const int grp = lane >> 4;          // 0: even edge of pair, 1: odd edge
    const int q = lane & 15;            // float4 slot within the 64-float row
    const int n = (blockIdx.x << 3) + (threadIdx.x >> 5);
    if (n >= N_NODES) return;
    const int beg = g_rowptr[n], end = g_rowptr[n + 1];

    unsigned long long a0 = 0ull, a1 = 0ull;
    const unsigned long long one2 = 0x3f8000003f800000ull;
    int j = beg;
    const int nb = (end - beg) >> 3;    // full 8-edge batches

    if (nb > 0) {
        // prologue: load batch 0 (scalar index loads — alignment-free)
        int c0 = g_ecol[j + 0 + grp];
        int c1 = g_ecol[j + 2 + grp];
        int c2 = g_ecol[j + 4 + grp];
        int c3 = g_ecol[j + 6 + grp];
        float4 v0 = *(const float4*)(S + (size_t)c0 * EMB + q * 4);
        float4 v1 = *(const float4*)(S + (size_t)c1 * EMB + q * 4);
        float4 v2 = *(const float4*)(S + (size_t)c2 * EMB + q * 4);
        float4 v3 = *(const float4*)(S + (size_t)c3 * EMB + q * 4);

        for (int b = 1; b < nb; b++) {
            j += 8;
            // issue next batch's loads BEFORE consuming current batch
            int d0 = g_ecol[j + 0 + grp];
            int d1 = g_ecol[j + 2 + grp];
            int d2 = g_ecol[j + 4 + grp];
            int d3 = g_ecol[j + 6 + grp];
            float4 w0 = *(const float4*)(S + (size_t)d0 * EMB + q * 4);
            float4 w1 = *(const float4*)(S + (size_t)d1 * EMB + q * 4);
            float4 w2 = *(const float4*)(S + (size_t)d2 * EMB + q * 4);
            float4 w3 = *(const float4*)(S + (size_t)d3 * EMB + q * 4);
            // consume current
            a0 = fma2(pk2(v0.x, v0.y), one2, a0);
            a1 = fma2(pk2(v0.z, v0.w), one2, a1);
            a0 = fma2(pk2(v1.x, v1.y), one2, a0);
            a1 = fma2(pk2(v1.z, v1.w), one2, a1);
            a0 = fma2(pk2(v2.x, v2.y), one2, a0);
            a1 = fma2(pk2(v2.z, v2.w), one2, a1);
            a0 = fma2(pk2(v3.x, v3.y), one2, a0);
            a1 = fma2(pk2(v3.z, v3.w), one2, a1);
            v0 = w0; v1 = w1; v2 = w2; v3 = w3;
        }
        // epilogue: consume last batch
        a0 = fma2(pk2(v0.x, v0.y), one2, a0);
        a1 = fma2(pk2(v0.z, v0.w), one2, a1);
        a0 = fma2(pk2(v1.x, v1.y), one2, a0);
        a1 = fma2(pk2(v1.z, v1.w), one2, a1);
        a0 = fma2(pk2(v2.x, v2.y), one2, a0);
        a1 = fma2(pk2(v2.z, v2.w), one2, a1);
        a0 = fma2(pk2(v3.x, v3.y), one2, a0);
        a1 = fma2(pk2(v3.z, v3.w), one2, a1);
        j += 8;
    }

    // remaining pairs
    for (; j + 2 <= end; j += 2) {
        int c = g_ecol[j + grp];
        float4 v = *(const float4*)(S + (size_t)c * EMB + q * 4);
        a0 = fma2(pk2(v.x, v.y), one2, a0);
        a1 = fma2(pk2(v.z, v.w), one2, a1);
    }
    // odd tail edge: group 0 only
    if (j < end && grp == 0) {
        int c = g_ecol[j];
        float4 v = *(const float4*)(S + (size_t)c * EMB + q * 4);
        a0 = fma2(pk2(v.x, v.y), one2, a0);
        a1 = fma2(pk2(v.z, v.w), one2, a1);
    }

    // merge half-warp accumulators
    float2 f0 = upk(a0), f1 = upk(a1);
    f0.x += __shfl_xor_sync(0xffffffffu, f0.x, 16);
    f0.y += __shfl_xor_sync(0xffffffffu, f0.y, 16);
    f1.x += __shfl_xor_sync(0xffffffffu, f1.x, 16);
    f1.y += __shfl_xor_sync(0xffffffffu, f1.y, 16);

    if (grp == 0) {
        float dn = g_dis[n];
        *(float4*)(xout + (size_t)n * EMB + q * 4) =
            make_float4(f0.x * dn, f0.y * dn, f1.x * dn, f1.y * dn);
    }
}

// ---------------- fused intent: y = softmax(X@W)@W^T; xio += y; out += xio/3 ----------------
#define LD1 130
#define LDP 130
#define LDW2 68
#define R1_FLOATS 16640
#define SMEMF_BYTES ((R1_FLOATS + 128 * LDW2) * 4)   // 101376 B

__global__ __launch_bounds__(256, 2) void fused_intent_kernel(
    const float* __restrict__ xin, const float* __restrict__ W,
    float* __restrict__ xio, float* __restrict__ out,
    float* __restrict__ Sout) {
    extern __shared__ float smem[];
    float* sXT = smem;                    // [64][LD1]
    float* sW  = smem + 64 * LD1;         // [64][128]
    float* sPT = smem;                    // [128][LDP]  (aliases after sync)
    float* sWT = smem + R1_FLOATS;        // [128][LDW2]

    const int tid = threadIdx.x;
    const int node0 = blockIdx.x * 128;

    for (int i = tid; i < 64 * 128 / 4; i += 256)
        *(float4*)(sW + i * 4) = *(const float4*)(W + i * 4);
    for (int i = tid; i < 64 * 128; i += 256) {
        int k = i >> 7, j = i & 127;
        sWT[j * LDW2 + k] = W[i];
    }
    for (int i = tid; i < 128 * 16; i += 256) {
        int m = i >> 4;
        int k4 = (i & 15) << 2;
        int nd = node0 + m;
        float4 v = (nd < N_NODES) ? *(const float4*)(xin + (size_t)nd * EMB + k4)
                                  : make_float4(0.f, 0.f, 0.f, 0.f);
        sXT[(k4 + 0) * LD1 + m] = v.x;
        sXT[(k4 + 1) * LD1 + m] = v.y;
        sXT[(k4 + 2) * LD1 + m] = v.z;
        sXT[(k4 + 3) * LD1 + m] = v.w;
    }
    __syncthreads();

    const int tj = tid & 15, tm = tid >> 4;
    const int m0 = tm * 8, j0 = tj * 8;
    unsigned long long acc[4][8];
    #pragma unroll
    for (int p = 0; p < 4; p++)
        #pragma unroll
        for (int c = 0; c < 8; c++) acc[p][c] = 0ull;

    #pragma unroll 8
    for (int k = 0; k < 64; k++) {
        unsigned long long a2[4];
        #pragma unroll
        for (int p = 0; p < 4; p++)
            a2[p] = *(const unsigned long long*)(sXT + k * LD1 + m0 + 2 * p);
        float4 b0 = *(const float4*)(sW + k * 128 + j0);
        float4 b1 = *(const float4*)(sW + k * 128 + j0 + 4);
        unsigned long long b2[8];
        b2[0] = pk2(b0.x, b0.x); b2[1] = pk2(b0.y, b0.y);
        b2[2] = pk2(b0.z, b0.z); b2[3] = pk2(b0.w, b0.w);
        b2[4] = pk2(b1.x, b1.x); b2[5] = pk2(b1.y, b1.y);
        b2[6] = pk2(b1.z, b1.z); b2[7] = pk2(b1.w, b1.w);
        #pragma unroll
        for (int p = 0; p < 4; p++)
            #pragma unroll
            for (int c = 0; c < 8; c++)
                acc[p][c] = fma2(a2[p], b2[c], acc[p][c]);
    }
    __syncthreads();

    #pragma unroll
    for (int p = 0; p < 4; p++) {
        float lo[8], hi[8];
        #pragma unroll
        for (int c = 0; c < 8; c++) {
            float2 t = upk(acc[p][c]);
            lo[c] = t.x; hi[c] = t.y;
        }
        float mx0 = lo[0], mx1 = hi[0];
        #pragma unroll
        for (int c = 1; c < 8; c++) { mx0 = fmaxf(mx0, lo[c]); mx1 = fmaxf(mx1, hi[c]); }
        #pragma unroll
        for (int o = 8; o > 0; o >>= 1) {
            mx0 = fmaxf(mx0, __shfl_xor_sync(0xffffffffu, mx0, o));
            mx1 = fmaxf(mx1, __shfl_xor_sync(0xffffffffu, mx1, o));
        }
        float s0 = 0.f, s1 = 0.f;
        #pragma unroll
        for (int c = 0; c < 8; c++) {
            lo[c] = __expf(lo[c] - mx0); s0 += lo[c];
            hi[c] = __expf(hi[c] - mx1); s1 += hi[c];
        }
        #pragma unroll
        for (int o = 8; o > 0; o >>= 1) {
            s0 += __shfl_xor_sync(0xffffffffu, s0, o);
            s1 += __shfl_xor_sync(0xffffffffu, s1, o);
        }
        float i0 = 1.0f / s0, i1 = 1.0f / s1;
        #pragma unroll
        for (int c = 0; c < 8; c++)
            *(unsigned long long*)(sPT + (size_t)(j0 + c) * LDP + m0 + 2 * p) =
                pk2(lo[c] * i0, hi[c] * i1);
    }
    __syncthreads();

    const int tn = tid & 15, tm2 = tid >> 4;
    const int mm0 = tm2 * 8, n0 = tn * 4;
    unsigned long long acc2[4][4];
    #pragma unroll
    for (int p = 0; p < 4; p++)
        #pragma unroll
        for (int c = 0; c < 4; c++) acc2[p][c] = 0ull;

    #pragma unroll 8
    for (int j = 0; j < 128; j++) {
        unsigned long long a2[4];
        #pragma unroll
        for (int p = 0; p < 4; p++)
            a2[p] = *(const unsigned long long*)(sPT + (size_t)j * LDP + mm0 + 2 * p);
        float4 b = *(const float4*)(sWT + j * LDW2 + n0);
        unsigned long long b2[4];
        b2[0] = pk2(b.x, b.x); b2[1] = pk2(b.y, b.y);
        b2[2] = pk2(b.z, b.z); b2[3] = pk2(b.w, b.w);
        #pragma unroll
        for (int p = 0; p < 4; p++)
            #pragma unroll
            for (int c = 0; c < 4; c++)
                acc2[p][c] = fma2(a2[p], b2[c], acc2[p][c]);
    }

    const float third = 1.0f / 3.0f;
    #pragma unroll
    for (int p = 0; p < 4; p++) {
        float2 t0 = upk(acc2[p][0]);
        float2 t1 = upk(acc2[p][1]);
        float2 t2 = upk(acc2[p][2]);
        float2 t3 = upk(acc2[p][3]);
        #pragma unroll
        for (int h = 0; h < 2; h++) {
            int nd = node0 + mm0 + 2 * p + h;
            if (nd < N_NODES) {
                size_t idx = (size_t)nd * EMB + n0;
                float y0 = h ? t0.y : t0.x, y1 = h ? t1.y : t1.x;
                float y2 = h ? t2.y : t2.x, y3 = h ? t3.y : t3.x;
                float4 g = *(const float4*)(xio + idx);
                float4 y = make_float4(y0 + g.x, y1 + g.y, y2 + g.z, y3 + g.w);
                *(float4*)(xio + idx) = y;
                float4 o = *(const float4*)(out + idx);
                o.x += y.x * third; o.y += y.y * third;
                o.z += y.z * third; o.w += y.w * third;
                *(float4*)(out + idx) = o;
                if (Sout) {
                    float d = g_dis[nd];
                    *(float4*)(Sout + idx) =
                        make_float4(y.x * d, y.y * d, y.z * d, y.w * d);
                }
            }
        }
    }
}

// ---------------- launch ----------------
extern "C" void kernel_launch(void* const* d_in, const int* in_sizes, int n_in,
                              void* d_out, int out_size) {
    const float* user = (const float*)d_in[0];
    const float* item = (const float*)d_in[1];
    const float* W    = (const float*)d_in[2];
    const int*   hix  = (const int*)d_in[3];
    const int*   tix  = (const int*)d_in[4];
    const int n_edges = in_sizes[3];
    float* out = (float*)d_out;

    cudaFuncSetAttribute(fused_intent_kernel,
                         cudaFuncAttributeMaxDynamicSharedMemorySize, SMEMF_BYTES);

    float *A, *B, *S;
    void *degp, *statep;
    cudaGetSymbolAddress((void**)&A, g_embA);
    cudaGetSymbolAddress((void**)&B, g_embB);
    cudaGetSymbolAddress((void**)&S, g_embS);
    cudaGetSymbolAddress(&degp, g_deg);
    cudaGetSymbolAddress(&statep, g_state);

    const int TB = 256;
    cudaMemsetAsync(degp, 0, N_NODES * sizeof(int));
    cudaMemsetAsync(statep, 0, NBLK * sizeof(unsigned long long));

    hist_kernel<<<4096, TB>>>(hix, n_edges);                               // kernel 1
    scan_kernel<<<NBLK, 1024>>>(n_edges);                                  // kernel 2
    scatter_init_kernel<<<4096, TB>>>(hix, tix, n_edges, user, item, A, out, S); // kernel 3

    const int spmm_blocks = (N_NODES + 7) / 8;
    const int tile_blocks = (N_NODES + 127) / 128;

    // layer 0
    spmm_kernel<<<spmm_blocks, TB>>>(S, B);                                // kernel 4 (profiled)
    fused_intent_kernel<<<tile_blocks, TB, SMEMF_BYTES>>>(A, W, B, out, S);
    // layer 1
    spmm_kernel<<<spmm_blocks, TB>>>(S, A);
    fused_intent_kernel<<<tile_blocks, TB, SMEMF_BYTES>>>(B, W, A, out, nullptr);
}

// round 9
// speedup vs baseline: 1.0270x; 1.0233x over previous
#include <cuda_runtime.h>
#include <cuda_fp16.h>
#include <math.h>

#define N_USERS 100000
#define N_ITEMS 50000
#define N_NODES 150000
#define EMB 64
#define NINT 128
#define MAX_EDGES 4000000

#define N4 ((N_NODES + 3) / 4)
#define NBLK ((N4 + 1023) / 1024)

// ---------------- static device scratch ----------------
__device__ int    g_deg[N_NODES];
__device__ float  g_dis[N_NODES];
__device__ int    g_rowptr[N_NODES + 1];
__device__ int    g_cursor[N_NODES];
__device__ int    g_ecol[MAX_EDGES];
__device__ volatile unsigned long long g_state[NBLK];
__device__ float  g_embA[(size_t)N_NODES * EMB];
__device__ float  g_embB[(size_t)N_NODES * EMB];
__device__ __half g_embS[(size_t)N_NODES * EMB];   // dis-scaled spmm input (fp16)

// ---------------- packed fp32x2 helpers ----------------
__device__ __forceinline__ unsigned long long fma2(unsigned long long a,
                                                   unsigned long long b,
                                                   unsigned long long c) {
    unsigned long long d;
    asm("fma.rn.f32x2 %0, %1, %2, %3;" : "=l"(d) : "l"(a), "l"(b), "l"(c));
    return d;
}
__device__ __forceinline__ unsigned long long pk2(float x, float y) {
    unsigned long long r;
    asm("mov.b64 %0, {%1, %2};" : "=l"(r) : "f"(x), "f"(y));
    return r;
}
__device__ __forceinline__ float2 upk(unsigned long long v) {
    float2 f;
    asm("mov.b64 {%0, %1}, %2;" : "=f"(f.x), "=f"(f.y) : "l"(v));
    return f;
}
__device__ __forceinline__ unsigned long long h2f2(unsigned int h) {
    float2 f = __half22float2(*(const __half2*)&h);
    return pk2(f.x, f.y);
}

// ---------------- precompute ----------------
__global__ void hist_kernel(const int* __restrict__ h, int n) {
    int stride = gridDim.x * blockDim.x;
    for (int i = blockIdx.x * blockDim.x + threadIdx.x; i < n; i += stride)
        atomicAdd(&g_deg[h[i]], 1);
}

// single-pass decoupled-lookback scan: deg -> rowptr/cursor (exclusive), dis
__global__ __launch_bounds__(1024) void scan_kernel(int n_edges) {
    __shared__ int ws[32];
    __shared__ int s_excl;
    const int t = threadIdx.x, b = blockIdx.x;
    const int lane = t & 31, wid = t >> 5;
    const int idx = b * 1024 + t;
    int4 v = (idx < N4) ? ((const int4*)g_deg)[idx] : make_int4(0, 0, 0, 0);
    int s = v.x + v.y + v.z + v.w;
    int x = s;
    #pragma unroll
    for (int o = 1; o < 32; o <<= 1) {
        int y = __shfl_up_sync(0xffffffffu, x, o);
        if (lane >= o) x += y;
    }
    if (lane == 31) ws[wid] = x;
    __syncthreads();
    if (wid == 0) {
        int z = ws[lane];
        #pragma unroll
        for (int o = 1; o < 32; o <<= 1) {
            int y = __shfl_up_sync(0xffffffffu, z, o);
            if (lane >= o) z += y;
        }
        ws[lane] = z;
    }
    __syncthreads();
    const int total = ws[31];

    if (t == 0) {
        if (b == 0) {
            g_state[0] = (2ull << 32) | (unsigned)total;
            s_excl = 0;
        } else {
            g_state[b] = (1ull << 32) | (unsigned)total;
            int excl = 0;
            int p = b - 1;
            while (true) {
                unsigned long long st;
                do { st = g_state[p]; } while ((st >> 32) == 0ull);
                excl += (int)(unsigned)st;
                if ((st >> 32) == 2ull) break;
                p--;
            }
            g_state[b] = (2ull << 32) | (unsigned)(excl + total);
            s_excl = excl;
        }
    }
    __syncthreads();

    int base = s_excl + ((wid > 0) ? ws[wid - 1] : 0) + (x - s);
    if (idx < N4) {
        int i = idx * 4;
        int e0 = base, e1 = e0 + v.x, e2 = e1 + v.y, e3 = e2 + v.z;
        g_rowptr[i + 0] = e0; g_cursor[i + 0] = e0;
        g_rowptr[i + 1] = e1; g_cursor[i + 1] = e1;
        g_rowptr[i + 2] = e2; g_cursor[i + 2] = e2;
        g_rowptr[i + 3] = e3; g_cursor[i + 3] = e3;
        g_dis[i + 0] = (v.x > 0) ? rsqrtf((float)v.x) : 0.0f;
        g_dis[i + 1] = (v.y > 0) ? rsqrtf((float)v.y) : 0.0f;
        g_dis[i + 2] = (v.z > 0) ? rsqrtf((float)v.z) : 0.0f;
        g_dis[i + 3] = (v.w > 0) ? rsqrtf((float)v.w) : 0.0f;
    }
    if (b == 0 && t == 0) g_rowptr[N_NODES] = n_edges;
}

// fused: CSR column scatter + embA/out/S initialization
__global__ void scatter_init_kernel(const int* __restrict__ h, const int* __restrict__ t,
                                    int n,
                                    const float* __restrict__ u, const float* __restrict__ it,
                                    float* __restrict__ embA, float* __restrict__ out,
                                    __half* __restrict__ S) {
    const int stride = gridDim.x * blockDim.x;
    const int tid0 = blockIdx.x * blockDim.x + threadIdx.x;
    const int total4 = N_NODES * EMB / 4;
    const int ub4 = N_USERS * EMB / 4;
    const float third = 1.0f / 3.0f;
    for (int i = tid0; i < total4; i += stride) {
        float4 v = (i < ub4) ? ((const float4*)u)[i] : ((const float4*)it)[i - ub4];
        ((float4*)embA)[i] = v;
        ((float4*)out)[i] = make_float4(v.x * third, v.y * third, v.z * third, v.w * third);
        float d = g_dis[i >> 4];
        ((__half2*)S)[i * 2 + 0] = __floats2half2_rn(v.x * d, v.y * d);
        ((__half2*)S)[i * 2 + 1] = __floats2half2_rn(v.z * d, v.w * d);
    }
    for (int i = tid0; i < n; i += stride) {
        int hh = h[i];
        int pos = atomicAdd(&g_cursor[hh], 1);
        g_ecol[pos] = t[i];
    }
}

// ---------------- SPMM: warp/node, fp16 rows, 8 lanes/row, 4 edges/step, pipelined ----------------
__global__ __launch_bounds__(256) void spmm_kernel(const __half* __restrict__ S,
                                                   float* __restrict__ xout) {
    const int lane = threadIdx.x & 31;
    const int grp = lane >> 3;          // which of 4 edges in the quad
    const int q = lane & 7;             // 16B slice of the 128B fp16 row
    const int n = (blockIdx.x << 3) + (threadIdx.x >> 5);
    if (n >= N_NODES) return;
    const int beg = g_rowptr[n], end = g_rowptr[n + 1];
    const uint4* S4 = (const uint4*)S;  // 16B chunks; row = 8 chunks

    unsigned long long a0 = 0ull, a1 = 0ull, a2 = 0ull, a3 = 0ull;
    const unsigned long long one2 = 0x3f8000003f800000ull;
    int j = beg;
    const int nq = (end - beg) >> 2;    // full 4-edge quads

    if (nq > 0) {
        int c = g_ecol[j + grp];
        uint4 v = S4[(size_t)c * 8 + q];
        for (int b = 1; b < nq; b++) {
            j += 4;
            int d = g_ecol[j + grp];
            uint4 w = S4[(size_t)d * 8 + q];
            a0 = fma2(h2f2(v.x), one2, a0);
            a1 = fma2(h2f2(v.y), one2, a1);
            a2 = fma2(h2f2(v.z), one2, a2);
            a3 = fma2(h2f2(v.w), one2, a3);
            v = w;
        }
        a0 = fma2(h2f2(v.x), one2, a0);
        a1 = fma2(h2f2(v.y), one2, a1);
        a2 = fma2(h2f2(v.z), one2, a2);
        a3 = fma2(h2f2(v.w), one2, a3);
        j += 4;
    }

    // tail: fewer than 4 edges; each group predicated on its edge existing
    if (j + grp < end) {
        int c = g_ecol[j + grp];
        uint4 v = S4[(size_t)c * 8 + q];
        a0 = fma2(h2f2(v.x), one2, a0);
        a1 = fma2(h2f2(v.y), one2, a1);
        a2 = fma2(h2f2(v.z), one2, a2);
        a3 = fma2(h2f2(v.w), one2, a3);
    }

    // reduce across the 4 groups (xor 8, xor 16); lanes with same q share columns
    float2 f0 = upk(a0), f1 = upk(a1), f2 = upk(a2), f3 = upk(a3);
    #pragma unroll
    for (int o = 8; o <= 16; o <<= 1) {
        f0.x += __shfl_xor_sync(0xffffffffu, f0.x, o);
        f0.y += __shfl_xor_sync(0xffffffffu, f0.y, o);
        f1.x += __shfl_xor_sync(0xffffffffu, f1.x, o);
        f1.y += __shfl_xor_sync(0xffffffffu, f1.y, o);
        f2.x += __shfl_xor_sync(0xffffffffu, f2.x, o);
        f2.y += __shfl_xor_sync(0xffffffffu, f2.y, o);
        f3.x += __shfl_xor_sync(0xffffffffu, f3.x, o);
        f3.y += __shfl_xor_sync(0xffffffffu, f3.y, o);
    }

    if (grp == 0) {
        float dn = g_dis[n];
        float* row = xout + (size_t)n * EMB + q * 8;
        *(float4*)(row)     = make_float4(f0.x * dn, f0.y * dn, f1.x * dn, f1.y * dn);
        *(float4*)(row + 4) = make_float4(f2.x * dn, f2.y * dn, f3.x * dn, f3.y * dn);
    }
}

// ---------------- fused intent: y = softmax(X@W)@W^T; xio += y; out += xio/3 ----------------
#define LD1 130
#define LDP 130
#define LDW2 68
#define R1_FLOATS 16640
#define SMEMF_BYTES ((R1_FLOATS + 128 * LDW2) * 4)   // 101376 B

__global__ __launch_bounds__(256, 2) void fused_intent_kernel(
    const float* __restrict__ xin, const float* __restrict__ W,
    float* __restrict__ xio, float* __restrict__ out,
    __half* __restrict__ Sout) {
    extern __shared__ float smem[];
    float* sXT = smem;                    // [64][LD1]
    float* sW  = smem + 64 * LD1;         // [64][128]
    float* sPT = smem;                    // [128][LDP]  (aliases after sync)
    float* sWT = smem + R1_FLOATS;        // [128][LDW2]

    const int tid = threadIdx.x;
    const int node0 = blockIdx.x * 128;

    for (int i = tid; i < 64 * 128 / 4; i += 256)
        *(float4*)(sW + i * 4) = *(const float4*)(W + i * 4);
    for (int i = tid; i < 64 * 128; i += 256) {
        int k = i >> 7, j = i & 127;
        sWT[j * LDW2 + k] = W[i];
    }
    for (int i = tid; i < 128 * 16; i += 256) {
        int m = i >> 4;
        int k4 = (i & 15) << 2;
        int nd = node0 + m;
        float4 v = (nd < N_NODES) ? *(const float4*)(xin + (size_t)nd * EMB + k4)
                                  : make_float4(0.f, 0.f, 0.f, 0.f);
        sXT[(k4 + 0) * LD1 + m] = v.x;
        sXT[(k4 + 1) * LD1 + m] = v.y;
        sXT[(k4 + 2) * LD1 + m] = v.z;
        sXT[(k4 + 3) * LD1 + m] = v.w;
    }
    __syncthreads();

    const int tj = tid & 15, tm = tid >> 4;
    const int m0 = tm * 8, j0 = tj * 8;
    unsigned long long acc[4][8];
    #pragma unroll
    for (int p = 0; p < 4; p++)
        #pragma unroll
        for (int c = 0; c < 8; c++) acc[p][c] = 0ull;

    #pragma unroll 8
    for (int k = 0; k < 64; k++) {
        unsigned long long a2[4];
        #pragma unroll
        for (int p = 0; p < 4; p++)
            a2[p] = *(const unsigned long long*)(sXT + k * LD1 + m0 + 2 * p);
        float4 b0 = *(const float4*)(sW + k * 128 + j0);
        float4 b1 = *(const float4*)(sW + k * 128 + j0 + 4);
        unsigned long long b2[8];
        b2[0] = pk2(b0.x, b0.x); b2[1] = pk2(b0.y, b0.y);
        b2[2] = pk2(b0.z, b0.z); b2[3] = pk2(b0.w, b0.w);
        b2[4] = pk2(b1.x, b1.x); b2[5] = pk2(b1.y, b1.y);
        b2[6] = pk2(b1.z, b1.z); b2[7] = pk2(b1.w, b1.w);
        #pragma unroll
        for (int p = 0; p < 4; p++)
            #pragma unroll
            for (int c = 0; c < 8; c++)
                acc[p][c] = fma2(a2[p], b2[c], acc[p][c]);
    }
    __syncthreads();

    #pragma unroll
    for (int p = 0; p < 4; p++) {
        float lo[8], hi[8];
        #pragma unroll
        for (int c = 0; c < 8; c++) {
            float2 t = upk(acc[p][c]);
            lo[c] = t.x; hi[c] = t.y;
        }
        float mx0 = lo[0], mx1 = hi[0];
        #pragma unroll
        for (int c = 1; c < 8; c++) { mx0 = fmaxf(mx0, lo[c]); mx1 = fmaxf(mx1, hi[c]); }
        #pragma unroll
        for (int o = 8; o > 0; o >>= 1) {
            mx0 = fmaxf(mx0, __shfl_xor_sync(0xffffffffu, mx0, o));
            mx1 = fmaxf(mx1, __shfl_xor_sync(0xffffffffu, mx1, o));
        }
        float s0 = 0.f, s1 = 0.f;
        #pragma unroll
        for (int c = 0; c < 8; c++) {
            lo[c] = __expf(lo[c] - mx0); s0 += lo[c];
            hi[c] = __expf(hi[c] - mx1); s1 += hi[c];
        }
        #pragma unroll
        for (int o = 8; o > 0; o >>= 1) {
            s0 += __shfl_xor_sync(0xffffffffu, s0, o);
            s1 += __shfl_xor_sync(0xffffffffu, s1, o);
        }
        float i0 = 1.0f / s0, i1 = 1.0f / s1;
        #pragma unroll
        for (int c = 0; c < 8; c++)
            *(unsigned long long*)(sPT + (size_t)(j0 + c) * LDP + m0 + 2 * p) =
                pk2(lo[c] * i0, hi[c] * i1);
    }
    __syncthreads();

    const int tn = tid & 15, tm2 = tid >> 4;
    const int mm0 = tm2 * 8, n0 = tn * 4;
    unsigned long long acc2[4][4];
    #pragma unroll
    for (int p = 0; p < 4; p++)
        #pragma unroll
        for (int c = 0; c < 4; c++) acc2[p][c] = 0ull;

    #pragma unroll 8
    for (int j = 0; j < 128; j++) {
        unsigned long long a2[4];
        #pragma unroll
        for (int p = 0; p < 4; p++)
            a2[p] = *(const unsigned long long*)(sPT + (size_t)j * LDP + mm0 + 2 * p);
        float4 b = *(const float4*)(sWT + j * LDW2 + n0);
        unsigned long long b2[4];
        b2[0] = pk2(b.x, b.x); b2[1] = pk2(b.y, b.y);
        b2[2] = pk2(b.z, b.z); b2[3] = pk2(b.w, b.w);
        #pragma unroll
        for (int p = 0; p < 4; p++)
            #pragma unroll
            for (int c = 0; c < 4; c++)
                acc2[p][c] = fma2(a2[p], b2[c], acc2[p][c]);
    }

    const float third = 1.0f / 3.0f;
    #pragma unroll
    for (int p = 0; p < 4; p++) {
        float2 t0 = upk(acc2[p][0]);
        float2 t1 = upk(acc2[p][1]);
        float2 t2 = upk(acc2[p][2]);
        float2 t3 = upk(acc2[p][3]);
        #pragma unroll
        for (int h = 0; h < 2; h++) {
            int nd = node0 + mm0 + 2 * p + h;
            if (nd < N_NODES) {
                size_t idx = (size_t)nd * EMB + n0;
                float y0 = h ? t0.y : t0.x, y1 = h ? t1.y : t1.x;
                float y2 = h ? t2.y : t2.x, y3 = h ? t3.y : t3.x;
                float4 g = *(const float4*)(xio + idx);
                float4 y = make_float4(y0 + g.x, y1 + g.y, y2 + g.z, y3 + g.w);
                *(float4*)(xio + idx) = y;
                float4 o = *(const float4*)(out + idx);
                o.x += y.x * third; o.y += y.y * third;
                o.z += y.z * third; o.w += y.w * third;
                *(float4*)(out + idx) = o;
                if (Sout) {
                    float d = g_dis[nd];
                    ((__half2*)(Sout + idx))[0] = __floats2half2_rn(y.x * d, y.y * d);
                    ((__half2*)(Sout + idx))[1] = __floats2half2_rn(y.z * d, y.w * d);
                }
            }
        }
    }
}

// ---------------- launch ----------------
extern "C" void kernel_launch(void* const* d_in, const int* in_sizes, int n_in,
                              void* d_out, int out_size) {
    const float* user = (const float*)d_in[0];
    const float* item = (const float*)d_in[1];
    const float* W    = (const float*)d_in[2];
    const int*   hix  = (const int*)d_in[3];
    const int*   tix  = (const int*)d_in[4];
    const int n_edges = in_sizes[3];
    float* out = (float*)d_out;

    cudaFuncSetAttribute(fused_intent_kernel,
                         cudaFuncAttributeMaxDynamicSharedMemorySize, SMEMF_BYTES);

    float *A, *B;
    __half* S;
    void *degp, *statep;
    cudaGetSymbolAddress((void**)&A, g_embA);
    cudaGetSymbolAddress((void**)&B, g_embB);
    cudaGetSymbolAddress((void**)&S, g_embS);
    cudaGetSymbolAddress(&degp, g_deg);
    cudaGetSymbolAddress(&statep, g_state);

    const int TB = 256;
    cudaMemsetAsync(degp, 0, N_NODES * sizeof(int));
    cudaMemsetAsync(statep, 0, NBLK * sizeof(unsigned long long));

    hist_kernel<<<4096, TB>>>(hix, n_edges);                               // kernel 1
    scan_kernel<<<NBLK, 1024>>>(n_edges);                                  // kernel 2
    scatter_init_kernel<<<4096, TB>>>(hix, tix, n_edges, user, item, A, out, S); // kernel 3

    const int spmm_blocks = (N_NODES + 7) / 8;
    const int tile_blocks = (N_NODES + 127) / 128;

    // layer 0
    spmm_kernel<<<spmm_blocks, TB>>>(S, B);                                // kernel 4 (profiled)
    fused_intent_kernel<<<tile_blocks, TB, SMEMF_BYTES>>>(A, W, B, out, S);
    // layer 1
    spmm_kernel<<<spmm_blocks, TB>>>(S, A);
    fused_intent_kernel<<<tile_blocks, TB, SMEMF_BYTES>>>(B, W, A, out, nullptr);
}